// round 4
// baseline (speedup 1.0000x reference)
#include <cuda_runtime.h>
#include <cstdint>

// out[c, i, j] = one_hot[i, c]      for c in [0,4)
// out[c, i, j] = one_hot[j, c-4]    for c in [4,8)
// one_hot: [L, 4] float32, L = 4096; out: [8, L, L] float32 (536.9 MB stores)
//
// R3: in-kernel DRAM=80.8%, issue=12% -> no per-thread overhead left; the
// ~19% DRAM bubble tracks the 13.8-wave launch (wave-transition drain/refill).
// R4: persistent grid-stride kernel, one wave (152 SMs x 8 CTAs), each block
// loops over tiles; stores stream continuously. Tile decomposition via
// shift/mask (host passes log2 of dims).

#define BLOCK 256
#define ROWS  8
#define MAX_L 4096

__device__ float g_oht[4][MAX_L];   // transposed one-hot, 64 KB scratch

__global__ void transpose_oh_kernel(const float* __restrict__ oh, int L)
{
    const int i = blockIdx.x * blockDim.x + threadIdx.x;
    if (i < L) {
        const float4 r = reinterpret_cast<const float4*>(oh)[i];  // row i of [L,4]
        g_oht[0][i] = r.x;
        g_oht[1][i] = r.y;
        g_oht[2][i] = r.z;
        g_oht[3][i] = r.w;
    }
}

// Tile = (plane c, 8-row strip i0, 256-wide float4 segment jb).
// t -> jb = t & jbMask; s = t >> jbLog; istrip = s & iMask; c = s >> iLog.
__global__ __launch_bounds__(BLOCK, 8)
void seq_embed_kernel(const float* __restrict__ oh, float4* __restrict__ out,
                      int L, int nTiles,
                      int jbLog, int jbMask, int iLog, int iMask)
{
    const int L4 = L >> 2;

    for (int t = blockIdx.x; t < nTiles; t += gridDim.x) {
        const int jb = t & jbMask;
        const int s  = t >> jbLog;
        const int i0 = (s & iMask) * ROWS;
        const int c  = s >> iLog;
        const int j4 = (jb << 8) + threadIdx.x;   // BLOCK = 256

        float4* p = out + ((size_t)c * L + (size_t)i0) * (size_t)L4 + (size_t)j4;

        if (c < 4) {
            // row-constant broadcast: 8 scalar broadcast loads (L1 hits)
            float vals[ROWS];
#pragma unroll
            for (int r = 0; r < ROWS; r++)
                vals[r] = __ldg(&oh[(i0 + r) * 4 + c]);
#pragma unroll
            for (int r = 0; r < ROWS; r++) {
                __stcs(p, make_float4(vals[r], vals[r], vals[r], vals[r]));
                p += L4;
            }
        } else {
            // column one-hot: one coalesced LDG.128, reused for 8 rows
            const float4 v = *reinterpret_cast<const float4*>(&g_oht[c - 4][j4 << 2]);
#pragma unroll
            for (int r = 0; r < ROWS; r++) {
                __stcs(p, v);
                p += L4;
            }
        }
    }
}

static int ilog2i(int x) { int l = 0; while ((1 << l) < x) l++; return l; }

extern "C" void kernel_launch(void* const* d_in, const int* in_sizes, int n_in,
                              void* d_out, int out_size)
{
    const float* oh = (const float*)d_in[0];
    const int L  = in_sizes[0] / 4;   // one_hot is [L, 4]
    const int L4 = L >> 2;

    transpose_oh_kernel<<<(L + 255) / 256, 256>>>(oh, L);

    const int nJB = L4 / BLOCK;       // 4 segments per row
    const int nI  = L / ROWS;         // 512 strips per plane
    const int nTiles = 8 * nI * nJB;  // 16384
    const int jbLog = ilog2i(nJB);
    const int iLog  = ilog2i(nI);

    // One persistent wave: 152 SMs x 8 CTAs (grid-stride handles any mismatch)
    const int nBlocks = 152 * 8;

    seq_embed_kernel<<<nBlocks, BLOCK>>>(oh, (float4*)d_out, L, nTiles,
                                         jbLog, nJB - 1, iLog, nI - 1);
}

// round 5
// speedup vs baseline: 1.0797x; 1.0797x over previous
#include <cuda_runtime.h>
#include <cstdint>

// out[c, i, j] = one_hot[i, c]      for c in [0,4)
// out[c, i, j] = one_hot[j, c-4]    for c in [4,8)
// one_hot: [L, 4] float32, L = 4096; out: [8, L, L] float32 (536.9 MB stores)
//
// R4 post-mortem: persistent grid regressed (occ 67.5%, DRAM 74%) -> reverted
// to oversubscribed grid. R5: fold the one_hot transpose into the main kernel
// via warp-shuffle gather (kills the 2nd launch). Bottom-plane warp: 4
// coalesced LDG.128 of raw one_hot rows + 16 SHFL -> per-thread float4,
// reused across a 16-row strip of streaming stores.

#define BLOCK 256
#define ROWS  16

__global__ __launch_bounds__(BLOCK, 8)
void seq_embed_kernel(const float* __restrict__ oh, float4* __restrict__ out, int L)
{
    const int c  = blockIdx.z;                              // 0..7 plane
    const int i0 = blockIdx.y * ROWS;                       // row-strip base
    const int j4 = blockIdx.x * BLOCK + threadIdx.x;        // float4 column
    const int L4 = L >> 2;

    float4* p = out + ((size_t)c * L + (size_t)i0) * (size_t)L4 + (size_t)j4;

    if (c < 4) {
        // row-constant broadcast: 16 scalar broadcast loads (1 wavefront each)
        float vals[ROWS];
#pragma unroll
        for (int r = 0; r < ROWS; r++)
            vals[r] = __ldg(&oh[(i0 + r) * 4 + c]);
#pragma unroll
        for (int r = 0; r < ROWS; r++) {
            __stcs(p, make_float4(vals[r], vals[r], vals[r], vals[r]));
            p += L4;
        }
    } else {
        // Column one-hot. Thread needs one_hot[4*j4 + r][cc], r=0..3.
        // Warp covers 128 consecutive rows: load them coalesced (4 x LDG.128,
        // lane-contiguous), extract channel cc, shuffle-redistribute.
        const int cc    = c - 4;
        const int lane  = threadIdx.x & 31;
        const int j4w   = j4 & ~31;          // warp-base float4 column
        const int rbase = 4 * j4w;           // warp-base row
        const float4* ohf4 = reinterpret_cast<const float4*>(oh);

        float e[4];
#pragma unroll
        for (int q = 0; q < 4; q++) {
            const float4 rv = __ldg(&ohf4[rbase + 32 * q + lane]);  // row rbase+32q+lane
            e[q] = (cc & 1) ? ((cc & 2) ? rv.w : rv.y)
                            : ((cc & 2) ? rv.z : rv.x);
        }

        // Row (4*lane + r) lives in load q = lane>>3, source lane 4*(lane&7)+r.
        const int qsel  = lane >> 3;
        const int sbase = 4 * (lane & 7);
        float ov[4];
#pragma unroll
        for (int r = 0; r < 4; r++) {
            const float s0 = __shfl_sync(0xffffffffu, e[0], sbase + r);
            const float s1 = __shfl_sync(0xffffffffu, e[1], sbase + r);
            const float s2 = __shfl_sync(0xffffffffu, e[2], sbase + r);
            const float s3 = __shfl_sync(0xffffffffu, e[3], sbase + r);
            ov[r] = (qsel == 0) ? s0 : (qsel == 1) ? s1 : (qsel == 2) ? s2 : s3;
        }
        const float4 v = make_float4(ov[0], ov[1], ov[2], ov[3]);

        // Same value for every row in the strip -> pure streaming stores.
#pragma unroll
        for (int r = 0; r < ROWS; r++) {
            __stcs(p, v);
            p += L4;
        }
    }
}

extern "C" void kernel_launch(void* const* d_in, const int* in_sizes, int n_in,
                              void* d_out, int out_size)
{
    const float* oh = (const float*)d_in[0];
    const int L  = in_sizes[0] / 4;   // one_hot is [L, 4]
    const int L4 = L >> 2;

    dim3 block(BLOCK);
    dim3 grid(L4 / BLOCK, L / ROWS, 8);   // (4, 256, 8) = 8192 blocks for L=4096
    seq_embed_kernel<<<grid, block>>>(oh, (float4*)d_out, L);
}

// round 6
// speedup vs baseline: 1.1509x; 1.0659x over previous
#include <cuda_runtime.h>
#include <cstdint>

// out[c, i, j] = one_hot[i, c]      for c in [0,4)
// out[c, i, j] = one_hot[j, c-4]    for c in [4,8)
// one_hot: [L, 4] float32, L = 4096; out: [8, L, L] float32 (536.9 MB stores)
//
// Wall-clock across rounds: strip-1/131072blk=75.5us, strip-8/16384=76.5,
// strip-16/8192=79.1, persistent=85.4 -> fine-grained oversubscribed grid is
// the winning regime. R6: single launch (drop transpose kernel), ROWS=4 /
// 32768 blocks, bottom-plane gather via per-block smem channel stage:
// coalesced LDG.128 -> extract channel -> conflict-free STS -> LDS.128.

#define BLOCK 256
#define ROWS  4

__global__ __launch_bounds__(BLOCK, 8)
void seq_embed_kernel(const float* __restrict__ oh, float4* __restrict__ out, int L)
{
    const int c  = blockIdx.z;                              // 0..7 plane (uniform per block)
    const int i0 = blockIdx.y * ROWS;                       // row-strip base
    const int j4 = blockIdx.x * BLOCK + threadIdx.x;        // float4 column
    const int L4 = L >> 2;

    float4* p = out + ((size_t)c * L + (size_t)i0) * (size_t)L4 + (size_t)j4;

    if (c < 4) {
        // row-constant broadcast: ROWS scalar broadcast loads (1 wavefront each)
        float vals[ROWS];
#pragma unroll
        for (int r = 0; r < ROWS; r++)
            vals[r] = __ldg(&oh[(i0 + r) * 4 + c]);
#pragma unroll
        for (int r = 0; r < ROWS; r++) {
            __stcs(p, make_float4(vals[r], vals[r], vals[r], vals[r]));
            p += L4;
        }
    } else {
        // Column one-hot: block needs channel cc of one_hot rows
        // [4*j4base, 4*j4base + 4*BLOCK). Stage via smem:
        //   coalesced LDG.128 (4 wavefronts/warp) -> extract cc ->
        //   stride-1 STS (conflict-free) -> LDS.128 (conflict-free).
        __shared__ float sch[4 * BLOCK];                    // 4 KB
        const int cc    = c - 4;
        const int rbase = blockIdx.x * (BLOCK * 4);         // one_hot row base
        const float4* ohf4 = reinterpret_cast<const float4*>(oh);

#pragma unroll
        for (int q = 0; q < 4; q++) {
            const float4 rv = __ldg(&ohf4[rbase + q * BLOCK + threadIdx.x]);
            sch[q * BLOCK + threadIdx.x] =
                (cc & 1) ? ((cc & 2) ? rv.w : rv.y)
                         : ((cc & 2) ? rv.z : rv.x);
        }
        __syncthreads();

        // Thread j4 stores rows 4*j4..4*j4+3 -> sch[4*tid..4*tid+3]
        const float4 v = *reinterpret_cast<const float4*>(&sch[4 * threadIdx.x]);
#pragma unroll
        for (int r = 0; r < ROWS; r++) {
            __stcs(p, v);
            p += L4;
        }
    }
}

extern "C" void kernel_launch(void* const* d_in, const int* in_sizes, int n_in,
                              void* d_out, int out_size)
{
    const float* oh = (const float*)d_in[0];
    const int L  = in_sizes[0] / 4;   // one_hot is [L, 4]
    const int L4 = L >> 2;

    dim3 block(BLOCK);
    dim3 grid(L4 / BLOCK, L / ROWS, 8);   // (4, 1024, 8) = 32768 blocks for L=4096
    seq_embed_kernel<<<grid, block>>>(oh, (float4*)d_out, L);
}

// round 7
// speedup vs baseline: 1.1533x; 1.0022x over previous
#include <cuda_runtime.h>
#include <cstdint>

// out[c, i, j] = one_hot[i, c]      for c in [0,4)
// out[c, i, j] = one_hot[j, c-4]    for c in [4,8)
// one_hot: [L, 4] float32, L = 4096; out: [8, L, L] float32 (536.9 MB stores)
//
// R6 (74.2us, DRAM 82.8%): single launch, strip-4, block-wide smem channel
// stage. R7: the staging is warp-local by construction (warp w only reads the
// 128 floats it staged), so drop __syncthreads -> per-warp smem slice +
// __syncwarp. Removes BAR waits and block-grain gather/store serialization.

#define BLOCK 256
#define ROWS  4

__global__ __launch_bounds__(BLOCK, 8)
void seq_embed_kernel(const float* __restrict__ oh, float4* __restrict__ out, int L)
{
    const int c  = blockIdx.z;                              // 0..7 plane (uniform per block)
    const int i0 = blockIdx.y * ROWS;                       // row-strip base
    const int j4 = blockIdx.x * BLOCK + threadIdx.x;        // float4 column
    const int L4 = L >> 2;

    float4* p = out + ((size_t)c * L + (size_t)i0) * (size_t)L4 + (size_t)j4;

    if (c < 4) {
        // row-constant broadcast: ROWS scalar broadcast loads (1 wavefront each)
        float vals[ROWS];
#pragma unroll
        for (int r = 0; r < ROWS; r++)
            vals[r] = __ldg(&oh[(i0 + r) * 4 + c]);
#pragma unroll
        for (int r = 0; r < ROWS; r++) {
            __stcs(p, make_float4(vals[r], vals[r], vals[r], vals[r]));
            p += L4;
        }
    } else {
        // Column one-hot, warp-local staging:
        // warp w covers j4 in [wbase, wbase+32) -> needs channel cc of one_hot
        // rows [4*wbase, 4*wbase+128). 4 coalesced LDG.128/lane -> extract cc
        // -> stride-1 STS into the warp's own 128-float slice -> __syncwarp ->
        // one conflict-free LDS.128 per lane. No block barrier.
        __shared__ float sch[4 * BLOCK];                    // 4 KB, 128 floats/warp
        const int cc    = c - 4;
        const int lane  = threadIdx.x & 31;
        const int warp  = threadIdx.x >> 5;
        const int wb4   = blockIdx.x * BLOCK + warp * 32;   // warp-base float4 column
        const int rbase = 4 * wb4;                          // warp-base one_hot row
        const float4* ohf4 = reinterpret_cast<const float4*>(oh);
        float* ws = &sch[warp * 128];

#pragma unroll
        for (int q = 0; q < 4; q++) {
            const float4 rv = __ldg(&ohf4[rbase + q * 32 + lane]);
            ws[q * 32 + lane] =
                (cc & 1) ? ((cc & 2) ? rv.w : rv.y)
                         : ((cc & 2) ? rv.z : rv.x);
        }
        __syncwarp();

        // Thread j4 stores rows 4*j4..4*j4+3 -> ws[4*lane .. 4*lane+3]
        const float4 v = *reinterpret_cast<const float4*>(&ws[4 * lane]);
#pragma unroll
        for (int r = 0; r < ROWS; r++) {
            __stcs(p, v);
            p += L4;
        }
    }
}

extern "C" void kernel_launch(void* const* d_in, const int* in_sizes, int n_in,
                              void* d_out, int out_size)
{
    const float* oh = (const float*)d_in[0];
    const int L  = in_sizes[0] / 4;   // one_hot is [L, 4]
    const int L4 = L >> 2;

    dim3 block(BLOCK);
    dim3 grid(L4 / BLOCK, L / ROWS, 8);   // (4, 1024, 8) = 32768 blocks for L=4096
    seq_embed_kernel<<<grid, block>>>(oh, (float4*)d_out, L);
}

// round 8
// speedup vs baseline: 1.1573x; 1.0035x over previous
#include <cuda_runtime.h>
#include <cstdint>

// out[c, i, j] = one_hot[i, c]      for c in [0,4)
// out[c, i, j] = one_hot[j, c-4]    for c in [4,8)
// one_hot: [L, 4] float32, L = 4096; out: [8, L, L] float32 (536.9 MB stores)
//
// R7 (74.1us, DRAM 82.4%): warp-local smem stage, strip-4. R8: top planes
// need no gather amortization (row value is constant), so remap top-plane
// blocks to one full contiguous 16KB row (thread stores 4 consecutive 4KB
// segments, 1 broadcast load instead of 4, single-page block footprint).
// Bottom planes keep the R7 strip-4 + warp-local smem stage.

#define BLOCK 256
#define ROWS  4
#define SEGS  4          // L4 / BLOCK for L=4096

__global__ __launch_bounds__(BLOCK, 8)
void seq_embed_kernel(const float* __restrict__ oh, float4* __restrict__ out, int L)
{
    const int c  = blockIdx.z;                              // 0..7 plane (uniform per block)
    const int L4 = L >> 2;

    if (c < 4) {
        // One block = one full row (16KB contiguous). Thread stores SEGS
        // consecutive 4KB segments of that row; value loaded once.
        const int row = blockIdx.y * SEGS + blockIdx.x;     // 0..L-1
        const float val = __ldg(&oh[row * 4 + c]);
        const float4 v = make_float4(val, val, val, val);

        float4* p = out + ((size_t)c * L + (size_t)row) * (size_t)L4 + threadIdx.x;
#pragma unroll
        for (int s = 0; s < SEGS; s++) {
            __stcs(p, v);
            p += BLOCK;
        }
    } else {
        // Column one-hot, warp-local staging (unchanged from R7):
        // 4 coalesced LDG.128/lane -> extract channel -> stride-1 STS into the
        // warp's own 128-float slice -> __syncwarp -> one LDS.128/lane,
        // value reused down a 4-row strip of streaming stores.
        __shared__ float sch[4 * BLOCK];                    // 4 KB, 128 floats/warp
        const int i0 = blockIdx.y * ROWS;                   // row-strip base
        const int j4 = blockIdx.x * BLOCK + threadIdx.x;    // float4 column
        const int cc    = c - 4;
        const int lane  = threadIdx.x & 31;
        const int warp  = threadIdx.x >> 5;
        const int wb4   = blockIdx.x * BLOCK + warp * 32;   // warp-base float4 column
        const int rbase = 4 * wb4;                          // warp-base one_hot row
        const float4* ohf4 = reinterpret_cast<const float4*>(oh);
        float* ws = &sch[warp * 128];

#pragma unroll
        for (int q = 0; q < 4; q++) {
            const float4 rv = __ldg(&ohf4[rbase + q * 32 + lane]);
            ws[q * 32 + lane] =
                (cc & 1) ? ((cc & 2) ? rv.w : rv.y)
                         : ((cc & 2) ? rv.z : rv.x);
        }
        __syncwarp();

        const float4 v = *reinterpret_cast<const float4*>(&ws[4 * lane]);
        float4* p = out + ((size_t)c * L + (size_t)i0) * (size_t)L4 + (size_t)j4;
#pragma unroll
        for (int r = 0; r < ROWS; r++) {
            __stcs(p, v);
            p += L4;
        }
    }
}

extern "C" void kernel_launch(void* const* d_in, const int* in_sizes, int n_in,
                              void* d_out, int out_size)
{
    const float* oh = (const float*)d_in[0];
    const int L  = in_sizes[0] / 4;   // one_hot is [L, 4]
    const int L4 = L >> 2;

    dim3 block(BLOCK);
    dim3 grid(L4 / BLOCK, L / ROWS, 8);   // (4, 1024, 8) = 32768 blocks for L=4096
    seq_embed_kernel<<<grid, block>>>(oh, (float4*)d_out, L);
}

// round 9
// speedup vs baseline: 1.1578x; 1.0004x over previous
#include <cuda_runtime.h>
#include <cstdint>

// out[c, i, j] = one_hot[i, c]      for c in [0,4)
// out[c, i, j] = one_hot[j, c-4]    for c in [4,8)
// one_hot: [L, 4] float32, L = 4096; out: [8, L, L] float32 (536.9 MB stores)
//
// R8 (73.8us, DRAM 82.6%): top planes = contiguous full-row blocks, bottom
// planes = strip-4 + warp-local smem channel stage. R9: z->plane remap
// {4,0,5,1,6,2,7,3} so the expensive gather planes launch FIRST and types
// alternate; kernel tail lands on the cheapest (broadcast) blocks and the
// DRAM store stream sees a steadier mix.

#define BLOCK 256
#define ROWS  4
#define SEGS  4          // L4 / BLOCK for L=4096

__constant__ int c_plane_order[8] = {4, 0, 5, 1, 6, 2, 7, 3};

__global__ __launch_bounds__(BLOCK, 8)
void seq_embed_kernel(const float* __restrict__ oh, float4* __restrict__ out, int L)
{
    const int c  = c_plane_order[blockIdx.z];               // 0..7 plane (uniform per block)
    const int L4 = L >> 2;

    if (c < 4) {
        // One block = one full row (16KB contiguous). Thread stores SEGS
        // consecutive 4KB segments of that row; value loaded once.
        const int row = blockIdx.y * SEGS + blockIdx.x;     // 0..L-1
        const float val = __ldg(&oh[row * 4 + c]);
        const float4 v = make_float4(val, val, val, val);

        float4* p = out + ((size_t)c * L + (size_t)row) * (size_t)L4 + threadIdx.x;
#pragma unroll
        for (int s = 0; s < SEGS; s++) {
            __stcs(p, v);
            p += BLOCK;
        }
    } else {
        // Column one-hot, warp-local staging:
        // 4 coalesced LDG.128/lane -> extract channel -> stride-1 STS into the
        // warp's own 128-float slice -> __syncwarp -> one LDS.128/lane,
        // value reused down a 4-row strip of streaming stores.
        __shared__ float sch[4 * BLOCK];                    // 4 KB, 128 floats/warp
        const int i0 = blockIdx.y * ROWS;                   // row-strip base
        const int j4 = blockIdx.x * BLOCK + threadIdx.x;    // float4 column
        const int cc    = c - 4;
        const int lane  = threadIdx.x & 31;
        const int warp  = threadIdx.x >> 5;
        const int wb4   = blockIdx.x * BLOCK + warp * 32;   // warp-base float4 column
        const int rbase = 4 * wb4;                          // warp-base one_hot row
        const float4* ohf4 = reinterpret_cast<const float4*>(oh);
        float* ws = &sch[warp * 128];

#pragma unroll
        for (int q = 0; q < 4; q++) {
            const float4 rv = __ldg(&ohf4[rbase + q * 32 + lane]);
            ws[q * 32 + lane] =
                (cc & 1) ? ((cc & 2) ? rv.w : rv.y)
                         : ((cc & 2) ? rv.z : rv.x);
        }
        __syncwarp();

        const float4 v = *reinterpret_cast<const float4*>(&ws[4 * lane]);
        float4* p = out + ((size_t)c * L + (size_t)i0) * (size_t)L4 + (size_t)j4;
#pragma unroll
        for (int r = 0; r < ROWS; r++) {
            __stcs(p, v);
            p += L4;
        }
    }
}

extern "C" void kernel_launch(void* const* d_in, const int* in_sizes, int n_in,
                              void* d_out, int out_size)
{
    const float* oh = (const float*)d_in[0];
    const int L  = in_sizes[0] / 4;   // one_hot is [L, 4]
    const int L4 = L >> 2;

    dim3 block(BLOCK);
    dim3 grid(L4 / BLOCK, L / ROWS, 8);   // (4, 1024, 8) = 32768 blocks for L=4096
    seq_embed_kernel<<<grid, block>>>(oh, (float4*)d_out, L);
}